// round 12
// baseline (speedup 1.0000x reference)
#include <cuda_runtime.h>
#include <cuda_bf16.h>

// SimSiam loss, algebraically reduced:
//   loss = -0.5 * sum_c( P_c . Z_c  -  sum_{i in c} pn_i.zn_i ) / npairs
// where P_c/Z_c are per-class sums of L2-normalized rows and
// npairs = sum_c m_c*(m_c-1)/2.   O(n*d) work, no 8192x8192 GEMM.
//
// TWO KERNELS + PDL: final_kernel launches with programmatic stream
// serialization, so its CTAs are resident and blocked at
// cudaGridDependencySynchronize() while accum runs — launch latency hidden.
// (All in-kernel fusion variants measured ~21us: barrier pays slowest-CTA
// spread + per-block gpu-scope fences; persistent small grid kills MLP.)
//
// accum processes TWO rows per warp: 4 independent float4 loads in flight
// before the shuffle-reduce chains (2x MLP of the 1-row version), half the
// blocks, half the per-block overhead.
//
// Pair count is incremental: atomicAdd(&cnt,1) returns old m; summing old
// m over a class's rows = m(m-1)/2. final never reads g_cnt (only zeros it).
//
// Scratch invariant: all accumulated __device__ scratch is ZERO at
// kernel_launch entry (zero at module load; final_kernel restores it).

#define NCLASS 512
#define D      128
#define EPS    1e-8f
#define FBLK   64          // final_kernel grid size / partial-slot count

__device__ float              g_P[NCLASS * D];
__device__ float              g_Z[NCLASS * D];
__device__ int                g_cnt[NCLASS];
__device__ double             g_Dpart[FBLK];     // diag partials
__device__ unsigned long long g_PairPart[FBLK];  // incremental pair partials
__device__ double             g_S;
__device__ unsigned long long g_pairs;
__device__ unsigned int       g_done;

// 128-bit reduction into global memory (sm_90+), no return value.
__device__ __forceinline__ void red_add_v4(float* p, float x, float y, float z, float w) {
    asm volatile("red.global.add.v4.f32 [%0], {%1, %2, %3, %4};"
                 :: "l"(p), "f"(x), "f"(y), "f"(z), "f"(w) : "memory");
}

// ---------------------------------------------------------------------------
// TWO rows per warp: 4 independent float4 loads, interleaved warp reductions,
// vector REDs into per-class sums. In-block dtype sniff (warp 0): first 64
// int64-view slots (512 B, in-bounds either way); an int32 buffer misdetects
// only if 64 consecutive odd labels are all zero (~2^-576).
__global__ void __launch_bounds__(256, 8)
accum_kernel(const float* __restrict__ ps,
             const float* __restrict__ zs,
             const void*  __restrict__ tgv,
             int n_rows) {
    __shared__ double       sdp[8];
    __shared__ unsigned int spr[8];
    __shared__ int          s_is64;

    int wid  = threadIdx.x >> 5;
    int lane = threadIdx.x & 31;
    int gw   = blockIdx.x * 8 + wid;       // global warp id
    int r0   = gw * 2;                     // this warp's two rows
    int r1   = r0 + 1;

    if (wid == 0) {
        const long long* t64 = (const long long*)tgv;
        int nslots = n_rows / 2;
        int k = (nslots < 64) ? nslots : 64;
        int bad = 0;
        for (int i = lane; i < k; i += 32) {
            long long v = __ldg(&t64[i]);
            if (v < 0 || v >= NCLASS) bad = 1;
        }
        bad = __any_sync(0xFFFFFFFFu, bad);
        if (lane == 0) s_is64 = !bad;
    }
    __syncthreads();
    int is64 = s_is64;

    double       diag = 0.0;
    unsigned int prow = 0u;
    if (r0 < n_rows) {
        // issue all 4 loads back-to-back (independent -> MLP 4)
        const float4* P4 = reinterpret_cast<const float4*>(ps);
        const float4* Z4 = reinterpret_cast<const float4*>(zs);
        float4 a0 = P4[r0 * (D / 4) + lane];
        float4 b0 = Z4[r0 * (D / 4) + lane];
        float4 a1 = P4[r1 * (D / 4) + lane];
        float4 b1 = Z4[r1 * (D / 4) + lane];

        float sa0 = a0.x * a0.x + a0.y * a0.y + a0.z * a0.z + a0.w * a0.w;
        float sb0 = b0.x * b0.x + b0.y * b0.y + b0.z * b0.z + b0.w * b0.w;
        float dp0 = a0.x * b0.x + a0.y * b0.y + a0.z * b0.z + a0.w * b0.w;
        float sa1 = a1.x * a1.x + a1.y * a1.y + a1.z * a1.z + a1.w * a1.w;
        float sb1 = b1.x * b1.x + b1.y * b1.y + b1.z * b1.z + b1.w * b1.w;
        float dp1 = a1.x * b1.x + a1.y * b1.y + a1.z * b1.z + a1.w * b1.w;

        #pragma unroll
        for (int o = 16; o > 0; o >>= 1) {
            sa0 += __shfl_xor_sync(0xFFFFFFFFu, sa0, o);
            sb0 += __shfl_xor_sync(0xFFFFFFFFu, sb0, o);
            dp0 += __shfl_xor_sync(0xFFFFFFFFu, dp0, o);
            sa1 += __shfl_xor_sync(0xFFFFFFFFu, sa1, o);
            sb1 += __shfl_xor_sync(0xFFFFFFFFu, sb1, o);
            dp1 += __shfl_xor_sync(0xFFFFFFFFu, dp1, o);
        }

        float invp0 = 1.0f / fmaxf(sqrtf(sa0), EPS);
        float invz0 = 1.0f / fmaxf(sqrtf(sb0), EPS);
        float invp1 = 1.0f / fmaxf(sqrtf(sa1), EPS);
        float invz1 = 1.0f / fmaxf(sqrtf(sb1), EPS);

        int t0, t1;
        if (is64) {
            t0 = (int)reinterpret_cast<const long long*>(tgv)[r0];
            t1 = (int)reinterpret_cast<const long long*>(tgv)[r1];
        } else {
            t0 = reinterpret_cast<const int*>(tgv)[r0];
            t1 = reinterpret_cast<const int*>(tgv)[r1];
        }

        red_add_v4(&g_P[t0 * D + lane * 4], a0.x * invp0, a0.y * invp0, a0.z * invp0, a0.w * invp0);
        red_add_v4(&g_Z[t0 * D + lane * 4], b0.x * invz0, b0.y * invz0, b0.z * invz0, b0.w * invz0);
        red_add_v4(&g_P[t1 * D + lane * 4], a1.x * invp1, a1.y * invp1, a1.z * invp1, a1.w * invp1);
        red_add_v4(&g_Z[t1 * D + lane * 4], b1.x * invz1, b1.y * invz1, b1.z * invz1, b1.w * invz1);

        if (lane == 0) {
            prow  = (unsigned int)atomicAdd(&g_cnt[t0], 1);
            prow += (unsigned int)atomicAdd(&g_cnt[t1], 1);
            diag  = (double)(dp0 * invp0 * invz0) + (double)(dp1 * invp1 * invz1);
        }
    }
    if (lane == 0) { sdp[wid] = diag; spr[wid] = prow; }
    __syncthreads();
    if (threadIdx.x == 0) {
        double s = sdp[0] + sdp[1] + sdp[2] + sdp[3]
                 + sdp[4] + sdp[5] + sdp[6] + sdp[7];
        unsigned int pr = spr[0] + spr[1] + spr[2] + spr[3]
                        + spr[4] + spr[5] + spr[6] + spr[7];
        int slot = blockIdx.x & (FBLK - 1);
        atomicAdd(&g_Dpart[slot], s);
        atomicAdd(&g_PairPart[slot], (unsigned long long)pr);
    }
}

// ---------------------------------------------------------------------------
// PDL consumer: CTAs launch while accum runs, block at the dependency sync,
// then per-class dots (warp per class, 8/block), ONE double atomic per block,
// fold own partial slots, re-zero scratch, last-block epilogue.
__global__ void final_kernel(float* __restrict__ out) {
    __shared__ double sdot[8];

    int lane = threadIdx.x & 31;
    int wid  = threadIdx.x >> 5;                 // 0..7
    int c    = blockIdx.x * 8 + wid;
    int idx  = c * (D / 4) + lane;

    cudaGridDependencySynchronize();

    float4 p = reinterpret_cast<const float4*>(g_P)[idx];
    float4 z = reinterpret_cast<const float4*>(g_Z)[idx];
    float dot = p.x * z.x + p.y * z.y + p.z * z.z + p.w * z.w;
    #pragma unroll
    for (int o = 16; o > 0; o >>= 1)
        dot += __shfl_xor_sync(0xFFFFFFFFu, dot, o);
    if (lane == 0) sdot[wid] = (double)dot;

    // Re-zero owned scratch (restores launch-entry invariant).
    float4 zero4 = make_float4(0.f, 0.f, 0.f, 0.f);
    reinterpret_cast<float4*>(g_P)[idx] = zero4;
    reinterpret_cast<float4*>(g_Z)[idx] = zero4;
    if (threadIdx.x < 8) g_cnt[blockIdx.x * 8 + threadIdx.x] = 0;

    __syncthreads();
    if (threadIdx.x == 0) {
        double s = sdot[0] + sdot[1] + sdot[2] + sdot[3]
                 + sdot[4] + sdot[5] + sdot[6] + sdot[7]
                 - g_Dpart[blockIdx.x];
        unsigned long long pr = g_PairPart[blockIdx.x];
        g_Dpart[blockIdx.x]    = 0.0;
        g_PairPart[blockIdx.x] = 0ull;
        atomicAdd(&g_S, s);                          // 64 atomics total
        atomicAdd(&g_pairs, pr);
        __threadfence();
        unsigned int done = atomicAdd(&g_done, 1u);
        if (done == (unsigned int)(FBLK - 1)) {
            double np = (g_pairs > 0ull) ? (double)g_pairs : 1.0;
            out[0] = (float)(-0.5 * g_S / np);
            g_S = 0.0; g_pairs = 0ull; g_done = 0u;
        }
    }
}

// ---------------------------------------------------------------------------
extern "C" void kernel_launch(void* const* d_in, const int* in_sizes, int n_in,
                              void* d_out, int out_size) {
    const float* ps  = (const float*)d_in[0];
    const float* zs  = (const float*)d_in[1];
    const void*  tgt = d_in[2];
    float*       out = (float*)d_out;

    int n_rows = in_sizes[0] / D;               // 8192
    int ablk   = (n_rows + 15) / 16;            // 512 blocks, 2 rows/warp

    accum_kernel<<<ablk, 256>>>(ps, zs, tgt, n_rows);

    // PDL: final_kernel scheduled during accum; blocks at grid sync.
    cudaLaunchConfig_t cfg = {};
    cfg.gridDim  = dim3(FBLK, 1, 1);
    cfg.blockDim = dim3(256, 1, 1);
    cfg.dynamicSmemBytes = 0;
    cfg.stream = 0;
    cudaLaunchAttribute attrs[1];
    attrs[0].id = cudaLaunchAttributeProgrammaticStreamSerialization;
    attrs[0].val.programmaticStreamSerializationAllowed = 1;
    cfg.attrs = attrs;
    cfg.numAttrs = 1;
    cudaLaunchKernelEx(&cfg, final_kernel, out);
}

// round 13
// speedup vs baseline: 1.3325x; 1.3325x over previous
#include <cuda_runtime.h>
#include <cuda_bf16.h>

// SimSiam loss, algebraically reduced:
//   loss = -0.5 * sum_c( P_c . Z_c  -  sum_{i in c} pn_i.zn_i ) / npairs
// where P_c/Z_c are per-class sums of L2-normalized rows and
// npairs = sum_c m_c*(m_c-1)/2.   O(n*d) work, no 8192x8192 GEMM.
//
// This is the byte-level revert to the measured-best (12.3us) round-4
// kernel body, plus ONE change: final_kernel launches with programmatic
// dependent launch (PDL), so its CTAs are scheduled during accum and block
// at cudaGridDependencySynchronize() — hiding the inter-kernel gap.
// Everything else left exactly as the champion: all "improvements" tried
// in rounds 5-12 (plain-store partials, 64-slot spreads, incremental pair
// counts, 2-row MLP, three fusion designs) measured within or worse than
// the +/-3us run-to-run noise envelope.
//
// Scratch invariant: all accumulated __device__ scratch is ZERO at
// kernel_launch entry (zero at module load; final_kernel re-zeros before
// finishing).

#define NCLASS 512
#define D      128
#define EPS    1e-8f

__device__ float              g_P[NCLASS * D];
__device__ float              g_Z[NCLASS * D];
__device__ int                g_cnt[NCLASS];
__device__ double             g_Ddiag;   // sum_i pn_i . zn_i
__device__ double             g_S;       // sum_c P_c . Z_c
__device__ unsigned long long g_pairs;   // sum_c m(m-1)/2
__device__ unsigned int       g_done;    // last-block counter for final kernel

// 128-bit reduction into global memory (sm_90+), no return value.
__device__ __forceinline__ void red_add_v4(float* p, float x, float y, float z, float w) {
    asm volatile("red.global.add.v4.f32 [%0], {%1, %2, %3, %4};"
                 :: "l"(p), "f"(x), "f"(y), "f"(z), "f"(w) : "memory");
}

// ---------------------------------------------------------------------------
// One warp per row: float4 loads, warp-reduce norms + dot, scatter normalized
// rows into per-class sums with 128-bit vector atomics. In-block dtype sniff:
// warp 0 reads the first 64 int64-view slots (512 B, in-bounds either way);
// an int32 buffer misdetects only if 64 consecutive odd labels are 0.
__global__ void accum_kernel(const float* __restrict__ ps,
                             const float* __restrict__ zs,
                             const void*  __restrict__ tgv,
                             int n_rows) {
    __shared__ double sdp[8];
    __shared__ int    s_is64;

    int warp_in_blk = threadIdx.x >> 5;
    int lane        = threadIdx.x & 31;
    int warp        = (blockIdx.x * blockDim.x + threadIdx.x) >> 5;

    if (warp_in_blk == 0) {
        const long long* t64 = (const long long*)tgv;
        int nslots = n_rows / 2;
        int k = (nslots < 64) ? nslots : 64;
        int bad = 0;
        for (int i = lane; i < k; i += 32) {
            long long v = __ldg(&t64[i]);
            if (v < 0 || v >= NCLASS) bad = 1;
        }
        bad = __any_sync(0xFFFFFFFFu, bad);
        if (lane == 0) s_is64 = !bad;
    }
    __syncthreads();
    int is64 = s_is64;

    double diag = 0.0;
    if (warp < n_rows) {
        float4 a = reinterpret_cast<const float4*>(ps)[warp * (D / 4) + lane];
        float4 b = reinterpret_cast<const float4*>(zs)[warp * (D / 4) + lane];

        float sa = a.x * a.x + a.y * a.y + a.z * a.z + a.w * a.w;
        float sb = b.x * b.x + b.y * b.y + b.z * b.z + b.w * b.w;
        float dp = a.x * b.x + a.y * b.y + a.z * b.z + a.w * b.w;

        #pragma unroll
        for (int o = 16; o > 0; o >>= 1) {
            sa += __shfl_xor_sync(0xFFFFFFFFu, sa, o);
            sb += __shfl_xor_sync(0xFFFFFFFFu, sb, o);
            dp += __shfl_xor_sync(0xFFFFFFFFu, dp, o);
        }

        float invp = 1.0f / fmaxf(sqrtf(sa), EPS);
        float invz = 1.0f / fmaxf(sqrtf(sb), EPS);

        int t;
        if (is64) t = (int)reinterpret_cast<const long long*>(tgv)[warp];
        else      t = reinterpret_cast<const int*>(tgv)[warp];

        red_add_v4(&g_P[t * D + lane * 4], a.x * invp, a.y * invp, a.z * invp, a.w * invp);
        red_add_v4(&g_Z[t * D + lane * 4], b.x * invz, b.y * invz, b.z * invz, b.w * invz);

        if (lane == 0) {
            atomicAdd(&g_cnt[t], 1);
            diag = (double)(dp * invp * invz);
        }
    }
    if (lane == 0) sdp[warp_in_blk] = diag;
    __syncthreads();
    if (threadIdx.x == 0) {
        double s = sdp[0] + sdp[1] + sdp[2] + sdp[3]
                 + sdp[4] + sdp[5] + sdp[6] + sdp[7];
        atomicAdd(&g_Ddiag, s);
    }
}

// ---------------------------------------------------------------------------
// PDL consumer. Fused: per-class dot (warp per class) + pair count + scratch
// re-zero + last-block epilogue. grid = NCLASS/8 blocks of 256 threads.
__global__ void final_kernel(float* __restrict__ out, int n_blocks) {
    int lane = threadIdx.x & 31;
    int wid  = threadIdx.x >> 5;                 // 0..7
    int c    = blockIdx.x * 8 + wid;             // class handled by this warp
    int idx  = c * (D / 4) + lane;               // float4 index into g_P/g_Z

    // Wait for accum_kernel's writes to be visible (PDL dependency).
    cudaGridDependencySynchronize();

    float4 p = reinterpret_cast<const float4*>(g_P)[idx];
    float4 z = reinterpret_cast<const float4*>(g_Z)[idx];
    float dot = p.x * z.x + p.y * z.y + p.z * z.z + p.w * z.w;
    #pragma unroll
    for (int o = 16; o > 0; o >>= 1)
        dot += __shfl_xor_sync(0xFFFFFFFFu, dot, o);

    if (lane == 0) {
        atomicAdd(&g_S, (double)dot);
        unsigned long long m = (unsigned long long)g_cnt[c];
        if (m > 1ull) atomicAdd(&g_pairs, m * (m - 1ull) / 2ull);
    }

    // Re-zero the slices this block owns (restores launch-entry invariant).
    float4 zero4 = make_float4(0.f, 0.f, 0.f, 0.f);
    reinterpret_cast<float4*>(g_P)[idx] = zero4;
    reinterpret_cast<float4*>(g_Z)[idx] = zero4;
    if (lane == 0) g_cnt[c] = 0;

    __syncthreads();
    __threadfence();
    if (threadIdx.x == 0) {
        unsigned int done = atomicAdd(&g_done, 1u);
        if (done == (unsigned int)(n_blocks - 1)) {
            // last block: epilogue + scalar reset
            double np = (g_pairs > 0ull) ? (double)g_pairs : 1.0;
            out[0] = (float)(-0.5 * (g_S - g_Ddiag) / np);
            g_S = 0.0; g_Ddiag = 0.0; g_pairs = 0ull;
            g_done = 0u;
        }
    }
}

// ---------------------------------------------------------------------------
extern "C" void kernel_launch(void* const* d_in, const int* in_sizes, int n_in,
                              void* d_out, int out_size) {
    const float* ps  = (const float*)d_in[0];
    const float* zs  = (const float*)d_in[1];
    const void*  tgt = d_in[2];
    float*       out = (float*)d_out;

    int n_rows = in_sizes[0] / D;   // 8192

    accum_kernel<<<(n_rows + 7) / 8, 256>>>(ps, zs, tgt, n_rows);

    // PDL: final_kernel scheduled during accum; blocks at grid sync.
    int fb = NCLASS / 8;            // 64 blocks
    cudaLaunchConfig_t cfg = {};
    cfg.gridDim  = dim3(fb, 1, 1);
    cfg.blockDim = dim3(256, 1, 1);
    cfg.dynamicSmemBytes = 0;
    cfg.stream = 0;
    cudaLaunchAttribute attrs[1];
    attrs[0].id = cudaLaunchAttributeProgrammaticStreamSerialization;
    attrs[0].val.programmaticStreamSerializationAllowed = 1;
    cfg.attrs = attrs;
    cfg.numAttrs = 1;
    cudaLaunchKernelEx(&cfg, final_kernel, out, fb);
}